// round 13
// baseline (speedup 1.0000x reference)
#include <cuda_runtime.h>
#include <math.h>

// ---------------- problem constants ----------------
constexpr int B_  = 8;
constexpr int N_  = 3136;   // H*W
constexpr int C_  = 128;
constexpr int NH_ = 4;
constexpr int D_  = 32;     // C/NH
constexpr int L_  = 9;      // WIN*WIN
constexpr int P_  = 49;     // PH*PW
constexpr int HW_ = 56;     // H == W
constexpr int BP_ = B_ * P_;  // 392 pooled rows
constexpr float SCALE_ = 0.08838834764831845f;  // C^-0.5

constexpr int WS_  = 144;   // padded weight column stride (tf32 ext matrices)
constexpr int XS_  = 132;   // padded x-tile row stride
constexpr int SMEM_GEMM = (64 * XS_ + 128 * WS_) * 4;   // 107520 B

// ---------------- device scratch (no allocation allowed) ----------------
__device__ __align__(16) float g_rv   [B_*N_*C_];     // relu(v + bias)
__device__ __align__(16) float g_xacc [B_*N_*C_];     // x_pool per (b,n,c)
__device__ __align__(16) float g_q    [B_*NH_*N_];    // q logits [b][h][n]
__device__ __align__(16) float g_ksum [B_*NH_*N_];    // sum_d k  [b][h][n]
__device__ __align__(16) float g_xp   [BP_*C_];       // pooled sums (pre /64)
__device__ float g_wl [B_*NH_*L_];
__device__ float g_ksb[NH_];                          // per-head summed k bias
__device__ __align__(16) float g_vwT2 [C_*C_];        // v weights [k][c] fp32 (attn kvp)
__device__ __align__(16) float g_ksw2 [NH_*C_];       // folded k weights [h][k] fp32
__device__ __align__(16) unsigned g_w0[C_*WS_];       // tf32 ext: v | qw | ksw | 0
__device__ __align__(16) unsigned g_w1[C_*WS_];       // tf32 ext: sr | 0
__device__ __align__(16) unsigned g_w2[C_*WS_];       // tf32 ext: proj | 0

__device__ __forceinline__ float gelu_exact(float v) {
    return 0.5f * v * (1.0f + erff(v * 0.70710678118654752f));
}
__device__ __forceinline__ unsigned tf32_of(float f) {
    unsigned u; asm("cvt.rna.tf32.f32 %0, %1;" : "=r"(u) : "f"(f)); return u;
}
__device__ __forceinline__ void mma_tf32(float* c, const unsigned* a,
                                         unsigned b0, unsigned b1) {
    asm volatile("mma.sync.aligned.m16n8k8.row.col.f32.tf32.tf32.f32 "
        "{%0,%1,%2,%3}, {%4,%5,%6,%7}, {%8,%9}, {%0,%1,%2,%3};"
        : "+f"(c[0]), "+f"(c[1]), "+f"(c[2]), "+f"(c[3])
        : "r"(a[0]), "r"(a[1]), "r"(a[2]), "r"(a[3]), "r"(b0), "r"(b1));
}

// ---------------- K0: weight prep + zero accumulators ----------------
__global__ void transpose_k(const float* __restrict__ kvw,
                            const float* __restrict__ kvb,
                            const float* __restrict__ qw,
                            const float* __restrict__ srw,
                            const float* __restrict__ pjw)
{
    int i = blockIdx.x * 256 + threadIdx.x;      // 72 blocks cover 128*144
    for (int j = i; j < BP_ * C_; j += 72 * 256) g_xp[j] = 0.f;
    if (i < B_ * NH_ * L_) g_wl[i] = 0.f;
    if (i >= C_ * WS_) return;
    int k = i / WS_, c = i % WS_;
    float v0 = 0.f, v1 = 0.f, v2 = 0.f;
    if (c < 128) {
        v0 = kvw[(128 + c) * 128 + k];           // v rows of kv_w
        v1 = srw[c * 128 + k];
        v2 = pjw[c * 128 + k];
        g_vwT2[k * 128 + c] = v0;                // fp32 [k][c] for attn kvp
    } else if (c < 132) {
        v0 = qw[(c - 128) * 128 + k];
    } else if (c < 136) {
        float s = 0.f;
        #pragma unroll
        for (int j = 0; j < D_; j++) s += kvw[((c - 132) * D_ + j) * 128 + k];
        v0 = s;
        g_ksw2[(c - 132) * 128 + k] = s;         // fp32 [h][k] for attn kpool
    }
    g_w0[i] = tf32_of(v0);
    g_w1[i] = tf32_of(v1);
    g_w2[i] = tf32_of(v2);
    if (i < NH_) {
        float s = 0.f;
        #pragma unroll
        for (int j = 0; j < D_; j++) s += kvb[i * D_ + j];
        g_ksb[i] = s;
    }
}

// ---------------- tf32 mma GEMM: 64 rows x 128(+8) cols per block, 8 warps ----------------
// MODE 0: rv = relu(x @ vw + vb); extra cols -> q [b][h][n], ksum
// MODE 1: gelu(x @ srw + b) -> pooled sums into g_xp (atomicAdd)
// MODE 2: out = (xacc + localmix) @ proj + b; aux0/1 = lt/lb (wlf inline)
template<int MODE>
__global__ __launch_bounds__(256) void gemm_k(const float* __restrict__ Xarg,
                                              const float* __restrict__ bias,
                                              float* __restrict__ Outarg,
                                              const float* __restrict__ aux0,
                                              const float* __restrict__ aux1)
{
    const unsigned* __restrict__ Wg = (MODE == 1) ? g_w1 : ((MODE == 2) ? g_w2 : g_w0);
    float* __restrict__ Out = (MODE == 0) ? g_rv : Outarg;

    extern __shared__ unsigned smem_u[];
    unsigned* xs = smem_u;                  // [64][132] tf32
    unsigned* ws = smem_u + 64 * XS_;       // [128][144] tf32
    __shared__ int bkt[64];
    __shared__ float wlf_s[NH_ * L_];

    const int t = threadIdx.x;
    const int lane = t & 31, w = t >> 5;
    const int g4 = lane >> 2, tg = lane & 3;
    const int wm = w >> 2, wn = w & 3;      // 2 x 4 warp grid
    const int rbase = wm * 32, cbase = wn * 32;
    const long row0 = (long)blockIdx.x * 64;

    // ---- fill x tile (fp32 -> tf32) ----
    if (MODE == 2) {
        int b = (int)(row0 / N_), n0 = (int)(row0 % N_);
        if (t < NH_ * L_)
            wlf_s[t] = aux0[t] + (float)N_ * aux1[t] + g_wl[b * NH_ * L_ + t];
        __syncthreads();
        const float4* xacc4 = reinterpret_cast<const float4*>(g_xacc);
        const float4* rv4   = reinterpret_cast<const float4*>(g_rv);
        #pragma unroll
        for (int i = 0; i < 8; i++) {
            int idx = t + i * 256;
            int r = idx >> 5, c4 = idx & 31;
            int n = n0 + r;
            int yy = n / HW_, xx = n - yy * HW_;
            const float* wf = wlf_s + (c4 >> 3) * L_;
            float4 y = xacc4[(row0 + r) * 32 + c4];
            #pragma unroll
            for (int l = 0; l < L_; l++) {
                int py = yy + l / 3 - 1, px = xx + l % 3 - 1;
                if (py >= 0 && py < HW_ && px >= 0 && px < HW_) {
                    float4 v = rv4[((long)b * N_ + py * HW_ + px) * 32 + c4];
                    float wl = wf[l];
                    y.x = fmaf(v.x, wl, y.x); y.y = fmaf(v.y, wl, y.y);
                    y.z = fmaf(v.z, wl, y.z); y.w = fmaf(v.w, wl, y.w);
                }
            }
            uint4 u = make_uint4(tf32_of(y.x), tf32_of(y.y), tf32_of(y.z), tf32_of(y.w));
            *reinterpret_cast<uint4*>(xs + r * XS_ + c4 * 4) = u;
        }
    } else {
        const float4* X4 = reinterpret_cast<const float4*>(Xarg + row0 * C_);
        #pragma unroll
        for (int i = 0; i < 8; i++) {
            int idx = t + i * 256;
            int r = idx >> 5, c4 = idx & 31;
            float4 v = X4[idx];
            uint4 u = make_uint4(tf32_of(v.x), tf32_of(v.y), tf32_of(v.z), tf32_of(v.w));
            *reinterpret_cast<uint4*>(xs + r * XS_ + c4 * 4) = u;
        }
    }
    // ---- fill weight tile ----
    {
        const uint4* W4 = reinterpret_cast<const uint4*>(Wg);
        uint4* ws4 = reinterpret_cast<uint4*>(ws);
        #pragma unroll
        for (int i = 0; i < 18; i++) ws4[t + i * 256] = W4[t + i * 256];
    }
    __syncthreads();

    float acc[2][4][4];
    #pragma unroll
    for (int mt = 0; mt < 2; mt++)
        #pragma unroll
        for (int nt = 0; nt < 4; nt++)
            #pragma unroll
            for (int j = 0; j < 4; j++) acc[mt][nt][j] = 0.f;
    float accE[2][4];
    #pragma unroll
    for (int mt = 0; mt < 2; mt++)
        #pragma unroll
        for (int j = 0; j < 4; j++) accE[mt][j] = 0.f;

    #pragma unroll
    for (int kk = 0; kk < 16; kk++) {
        unsigned a[2][4];
        const unsigned* xa = xs + (rbase + g4) * XS_ + kk * 8 + tg;
        #pragma unroll
        for (int mt = 0; mt < 2; mt++) {
            const unsigned* x2 = xa + mt * 16 * XS_;
            a[mt][0] = x2[0];
            a[mt][1] = x2[8 * XS_];
            a[mt][2] = x2[4];
            a[mt][3] = x2[8 * XS_ + 4];
        }
        const unsigned* wb = ws + (kk * 8 + tg) * WS_ + g4;
        #pragma unroll
        for (int nt = 0; nt < 4; nt++) {
            unsigned b0 = wb[cbase + nt * 8];
            unsigned b1 = wb[4 * WS_ + cbase + nt * 8];
            mma_tf32(acc[0][nt], a[0], b0, b1);
            mma_tf32(acc[1][nt], a[1], b0, b1);
        }
        if (MODE == 0 && wn == 0) {
            unsigned b0 = wb[128];
            unsigned b1 = wb[4 * WS_ + 128];
            mma_tf32(accE[0], a[0], b0, b1);
            mma_tf32(accE[1], a[1], b0, b1);
        }
    }

    if (MODE == 1) {
        // gelu tile -> smem (reuse ws), then bucketed pool reduction -> g_xp
        __syncthreads();
        float* gt = reinterpret_cast<float*>(ws);   // [64][128]
        #pragma unroll
        for (int mt = 0; mt < 2; mt++) {
            #pragma unroll
            for (int nt = 0; nt < 4; nt++) {
                int col = cbase + nt * 8 + 2 * tg;
                float b0 = bias[col], b1 = bias[col + 1];
                #pragma unroll
                for (int half = 0; half < 2; half++) {
                    int r = rbase + mt * 16 + g4 + half * 8;
                    float v0 = gelu_exact(acc[mt][nt][half * 2 + 0] + b0);
                    float v1 = gelu_exact(acc[mt][nt][half * 2 + 1] + b1);
                    *reinterpret_cast<float2*>(gt + r * 128 + col) = make_float2(v0, v1);
                }
            }
        }
        int b = (int)(row0 / N_), n0 = (int)(row0 % N_);
        if (t < 64) {
            int n = n0 + t, y = n / HW_, x = n - y * HW_;
            bkt[t] = (y >> 3) * 7 + (x >> 3);
        }
        __syncthreads();
        int col = t & 127, half = t >> 7;
        int r0 = half * 32;
        float a = 0.f;
        int cur = bkt[r0];
        #pragma unroll 4
        for (int r = r0; r < r0 + 32; r++) {
            int bk = bkt[r];
            if (bk != cur) {
                atomicAdd(&g_xp[((long)b * P_ + cur) * C_ + col], a);
                a = 0.f; cur = bk;
            }
            a += gt[r * 128 + col];
        }
        atomicAdd(&g_xp[((long)b * P_ + cur) * C_ + col], a);
        return;
    }

    // ---- main epilogue ----
    #pragma unroll
    for (int mt = 0; mt < 2; mt++) {
        #pragma unroll
        for (int nt = 0; nt < 4; nt++) {
            int col = cbase + nt * 8 + 2 * tg;
            float b0 = bias[col], b1 = bias[col + 1];
            #pragma unroll
            for (int half = 0; half < 2; half++) {
                long rl = row0 + rbase + mt * 16 + g4 + half * 8;
                float v0 = acc[mt][nt][half * 2 + 0] + b0;
                float v1 = acc[mt][nt][half * 2 + 1] + b1;
                if (MODE == 0) { v0 = fmaxf(v0, 0.f); v1 = fmaxf(v1, 0.f); }
                *reinterpret_cast<float2*>(Out + rl * C_ + col) = make_float2(v0, v1);
            }
        }
    }

    // ---- extra-column epilogue (MODE 0: q+ksum) ----
    if (MODE == 0 && wn == 0) {
        #pragma unroll
        for (int mt = 0; mt < 2; mt++) {
            #pragma unroll
            for (int half = 0; half < 2; half++) {
                long grow = row0 + rbase + mt * 16 + g4 + half * 8;
                int b = (int)(grow / N_), n = (int)(grow % N_);
                #pragma unroll
                for (int j = 0; j < 2; j++) {
                    int col = 128 + 2 * tg + j;
                    float v = accE[mt][half * 2 + j];
                    if (col < 132) {
                        g_q[((long)b * NH_ + (col - 128)) * N_ + n] = v;
                    } else {
                        int h = col - 132;
                        g_ksum[((long)b * NH_ + h) * N_ + n] = v + g_ksb[h];
                    }
                }
            }
        }
    }
}

// ---------------- K4: LN+kvp (in-block) + denom + 58-way softmax + x_pool ----------------
constexpr int PS_ = 132;   // padded xsn row stride
__global__ __launch_bounds__(256) void attn_k(const float* __restrict__ pbp,
                                              const float* __restrict__ pbl,
                                              const float* __restrict__ nw,
                                              const float* __restrict__ nb,
                                              const float* __restrict__ kvb)
{
    int bh = blockIdx.y;
    int b  = bh >> 2, h = bh & 3;
    int n0 = blockIdx.x * 64;
    int t = threadIdx.x, lane = t & 31, wid = t >> 5;

    __shared__ float xsn[P_ * PS_];     // layernormed pooled rows (25.9 KB)
    __shared__ float vps[P_ * D_];
    __shared__ float kps[P_ + 1];
    __shared__ float asb[8][64];
    __shared__ float wlsh[8][L_];
    __shared__ float sh8[8];

    // ---- phase A: layernorm pooled rows (warp per row, strided) ----
    for (int p = wid; p < P_; p += 8) {
        float4 s = reinterpret_cast<const float4*>(g_xp)[((long)b * P_ + p) * 32 + lane];
        s.x *= (1.f/64.f); s.y *= (1.f/64.f); s.z *= (1.f/64.f); s.w *= (1.f/64.f);
        float tot = s.x + s.y + s.z + s.w;
        #pragma unroll
        for (int o = 16; o; o >>= 1) tot += __shfl_xor_sync(~0u, tot, o);
        float mu = tot * (1.f / C_);
        float dx = s.x - mu, dy = s.y - mu, dz = s.z - mu, dw = s.w - mu;
        float sq = dx * dx + dy * dy + dz * dz + dw * dw;
        #pragma unroll
        for (int o = 16; o; o >>= 1) sq += __shfl_xor_sync(~0u, sq, o);
        float inv = rsqrtf(sq * (1.f / C_) + 1e-5f);
        float4 w4 = reinterpret_cast<const float4*>(nw)[lane];
        float4 b4 = reinterpret_cast<const float4*>(nb)[lane];
        float4 xn;
        xn.x = dx * inv * w4.x + b4.x; xn.y = dy * inv * w4.y + b4.y;
        xn.z = dz * inv * w4.z + b4.z; xn.w = dw * inv * w4.w + b4.w;
        *reinterpret_cast<float4*>(xsn + p * PS_ + lane * 4) = xn;
    }
    __syncthreads();

    // ---- phase B: v_pool matvec (thread owns col d=lane for rows p=wid+8j) ----
    {
        int c = h * D_ + lane;
        float vb = kvb[C_ + c];
        float acc[7];
        #pragma unroll
        for (int j = 0; j < 7; j++) acc[j] = vb;
        int np = (P_ - wid + 7) >> 3;           // rows this thread handles
        const float* wv = g_vwT2 + c;
        #pragma unroll 4
        for (int k = 0; k < C_; k++) {
            float wk = wv[k * 128];             // coalesced across lanes
            #pragma unroll
            for (int j = 0; j < 7; j++) {
                int p = wid + j * 8;
                if (p < P_) acc[j] = fmaf(wk, xsn[p * PS_ + k], acc[j]);
            }
        }
        #pragma unroll
        for (int j = 0; j < 7; j++) {
            int p = wid + j * 8;
            if (p < P_) vps[p * D_ + lane] = acc[j];
        }
        // k_pool: threads 0..48 each one dot against folded k weights
        if (t < P_) {
            float a = g_ksb[h];
            const float* wk2 = g_ksw2 + h * C_;
            #pragma unroll 4
            for (int k = 0; k < C_; k++) a = fmaf(wk2[k], xsn[t * PS_ + k], a);
            kps[t] = a;
        }
    }

    // ---- phase C: context-softmax denominator (per-block recompute) ----
    const float* qp = g_q + (long)bh * N_;
    float s = 0.f;
    for (int n = t; n < N_; n += 256) s += __expf(qp[n]);
    #pragma unroll
    for (int o = 16; o; o >>= 1) s += __shfl_xor_sync(~0u, s, o);
    if (lane == 0) sh8[wid] = s;
    __syncthreads();
    float S = sh8[0];
    #pragma unroll
    for (int ww = 1; ww < 8; ww++) S += sh8[ww];
    float invS = 1.f / S;

    const float NEG = -INFINITY;
    float wlacc = 0.f;
    float pbl_l = (lane < L_) ? pbl[h * L_ + lane] : 0.f;

    for (int i = 0; i < 8; i++) {
        int n = n0 + wid * 8 + i;
        float cs  = __expf(qp[n]) * invS;
        float csS = cs * SCALE_;
        const float* pbpn = pbp + ((long)h * N_ + n) * P_;

        float v0, v1 = NEG;
        if (lane < L_) {
            int y = n / HW_ + lane / 3 - 1, x = n % HW_ + lane % 3 - 1;
            v0 = (y >= 0 && y < HW_ && x >= 0 && x < HW_)
                 ? g_ksum[(long)bh * N_ + y * HW_ + x] * csS + pbl_l : NEG;
        } else {
            int p = lane - L_;
            v0 = csS * kps[p] + pbpn[p];
        }
        if (lane < 26) { int p = lane + 23; v1 = csS * kps[p] + pbpn[p]; }

        float e0 = __expf(v0);
        float e1 = (lane < 26) ? __expf(v1) : 0.f;
        float se = e0 + e1;
        #pragma unroll
        for (int o = 16; o; o >>= 1) se += __shfl_xor_sync(0xffffffffu, se, o);
        float inv = 1.f / se;
        e0 *= inv; e1 *= inv;

        if (lane < L_) wlacc += e0;
        asb[wid][lane] = e0;
        if (lane < 26) asb[wid][lane + 32] = e1;
        __syncwarp();

        float acc = 0.f;
        #pragma unroll
        for (int p = 0; p < P_; p++)
            acc = fmaf(asb[wid][L_ + p], vps[p * D_ + lane], acc);
        g_xacc[((long)b * N_ + n) * C_ + h * D_ + lane] = acc;
        __syncwarp();
    }

    if (lane < L_) wlsh[wid][lane] = wlacc;
    __syncthreads();
    if (t < L_) {
        float sl = 0.f;
        #pragma unroll
        for (int ww = 0; ww < 8; ww++) sl += wlsh[ww][t];
        atomicAdd(&g_wl[bh * L_ + t], sl);
    }
}

// ---------------- launch ----------------
extern "C" void kernel_launch(void* const* d_in, const int* in_sizes, int n_in,
                              void* d_out, int out_size)
{
    const float* x    = (const float*)d_in[0];
    const float* q_w  = (const float*)d_in[1];
    const float* kv_w = (const float*)d_in[4];
    const float* kv_b = (const float*)d_in[5];
    const float* sr_w = (const float*)d_in[6];
    const float* sr_b = (const float*)d_in[7];
    const float* nw   = (const float*)d_in[8];
    const float* nb   = (const float*)d_in[9];
    const float* pbp  = (const float*)d_in[10];
    const float* pbl  = (const float*)d_in[11];
    const float* lt   = (const float*)d_in[12];
    const float* lb   = (const float*)d_in[13];
    const float* pjw  = (const float*)d_in[14];
    const float* pjb  = (const float*)d_in[15];
    float* out = (float*)d_out;

    static bool attr_set = false;
    if (!attr_set) {
        cudaFuncSetAttribute(gemm_k<0>, cudaFuncAttributeMaxDynamicSharedMemorySize, SMEM_GEMM);
        cudaFuncSetAttribute(gemm_k<1>, cudaFuncAttributeMaxDynamicSharedMemorySize, SMEM_GEMM);
        cudaFuncSetAttribute(gemm_k<2>, cudaFuncAttributeMaxDynamicSharedMemorySize, SMEM_GEMM);
        attr_set = true;
    }

    transpose_k<<<72, 256>>>(kv_w, kv_b, q_w, sr_w, pjw);     // weights + zero accums
    gemm_k<0><<<392, 256, SMEM_GEMM>>>(x, kv_b + C_, nullptr, nullptr, nullptr);  // relu(v)+q+ksum
    gemm_k<1><<<392, 256, SMEM_GEMM>>>(x, sr_b, nullptr, nullptr, nullptr);       // gelu(sr)+pool
    dim3 g4(49, B_ * NH_);
    attn_k<<<g4, 256>>>(pbp, pbl, nw, nb, kv_b);              // LN+kvp+softmax+x_pool
    gemm_k<2><<<392, 256, SMEM_GEMM>>>(nullptr, pjb, out, lt, lb);  // wlf+localmix+proj
}

// round 14
// speedup vs baseline: 1.2499x; 1.2499x over previous
#include <cuda_runtime.h>
#include <math.h>

// ---------------- problem constants ----------------
constexpr int B_  = 8;
constexpr int N_  = 3136;   // H*W
constexpr int C_  = 128;
constexpr int NH_ = 4;
constexpr int D_  = 32;     // C/NH
constexpr int L_  = 9;      // WIN*WIN
constexpr int P_  = 49;     // PH*PW
constexpr int HW_ = 56;     // H == W
constexpr int BP_ = B_ * P_;  // 392 pooled rows
constexpr float SCALE_ = 0.08838834764831845f;  // C^-0.5

constexpr int WS_  = 144;   // padded weight column stride (tf32 ext matrices)
constexpr int XS_  = 132;   // padded x-tile row stride
constexpr int SMEM_GEMM = (64 * XS_ + 128 * WS_) * 4;   // 107520 B

// ---------------- device scratch (no allocation allowed) ----------------
__device__ __align__(16) float g_rv   [B_*N_*C_];     // relu(v + bias)
__device__ __align__(16) float g_xacc [B_*N_*C_];     // x_pool per (b,n,c)
__device__ __align__(16) float g_q    [B_*NH_*N_];    // q logits [b][h][n]
__device__ __align__(16) float g_ksum [B_*NH_*N_];    // sum_d k  [b][h][n]
__device__ __align__(16) float g_xp   [BP_*C_];       // pooled sums (pre /64)
__device__ __align__(16) float g_kpool[B_*NH_*P_];
__device__ __align__(16) float g_vpool[B_*NH_*P_*D_];
__device__ float g_wl [B_*NH_*L_];
__device__ float g_ksb[NH_];                          // per-head summed k bias
__device__ __align__(16) unsigned g_w0[C_*WS_];       // tf32 ext: v | qw | ksw | 0
__device__ __align__(16) unsigned g_w1[C_*WS_];       // tf32 ext: sr | 0
__device__ __align__(16) unsigned g_w2[C_*WS_];       // tf32 ext: proj | 0

__device__ __forceinline__ float gelu_exact(float v) {
    return 0.5f * v * (1.0f + erff(v * 0.70710678118654752f));
}
__device__ __forceinline__ unsigned tf32_of(float f) {
    unsigned u; asm("cvt.rna.tf32.f32 %0, %1;" : "=r"(u) : "f"(f)); return u;
}
__device__ __forceinline__ void mma_tf32(float* c, const unsigned* a,
                                         unsigned b0, unsigned b1) {
    asm volatile("mma.sync.aligned.m16n8k8.row.col.f32.tf32.tf32.f32 "
        "{%0,%1,%2,%3}, {%4,%5,%6,%7}, {%8,%9}, {%0,%1,%2,%3};"
        : "+f"(c[0]), "+f"(c[1]), "+f"(c[2]), "+f"(c[3])
        : "r"(a[0]), "r"(a[1]), "r"(a[2]), "r"(a[3]), "r"(b0), "r"(b1));
}

// ---------------- K0: weight prep + zero accumulators ----------------
__global__ void transpose_k(const float* __restrict__ kvw,
                            const float* __restrict__ kvb,
                            const float* __restrict__ qw,
                            const float* __restrict__ srw,
                            const float* __restrict__ pjw)
{
    int i = blockIdx.x * 256 + threadIdx.x;      // 72 blocks cover 128*144
    for (int j = i; j < BP_ * C_; j += 72 * 256) g_xp[j] = 0.f;
    for (int j = i; j < B_ * NH_ * P_ * D_; j += 72 * 256) g_vpool[j] = 0.f;
    if (i < B_ * NH_ * P_) g_kpool[i] = 0.f;
    if (i < B_ * NH_ * L_) g_wl[i] = 0.f;
    if (i >= C_ * WS_) return;
    int k = i / WS_, c = i % WS_;
    float v0 = 0.f, v1 = 0.f, v2 = 0.f;
    if (c < 128) {
        v0 = kvw[(128 + c) * 128 + k];           // v rows of kv_w
        v1 = srw[c * 128 + k];
        v2 = pjw[c * 128 + k];
    } else if (c < 132) {
        v0 = qw[(c - 128) * 128 + k];
    } else if (c < 136) {
        float s = 0.f;
        #pragma unroll
        for (int j = 0; j < D_; j++) s += kvw[((c - 132) * D_ + j) * 128 + k];
        v0 = s;
    }
    g_w0[i] = tf32_of(v0);
    g_w1[i] = tf32_of(v1);
    g_w2[i] = tf32_of(v2);
    if (i < NH_) {
        float s = 0.f;
        #pragma unroll
        for (int j = 0; j < D_; j++) s += kvb[i * D_ + j];
        g_ksb[i] = s;
    }
}

// ---------------- tf32 mma GEMM (modes 1 & 2, as in R12) ----------------
// MODE 1: gelu(x @ srw + b) -> pooled sums into g_xp (atomicAdd)
// MODE 2: out = (xacc + localmix) @ proj + b; aux0/1 = lt/lb (wlf inline)
template<int MODE>
__global__ __launch_bounds__(256) void gemm_k(const float* __restrict__ Xarg,
                                              const float* __restrict__ bias,
                                              float* __restrict__ Outarg,
                                              const float* __restrict__ aux0,
                                              const float* __restrict__ aux1)
{
    const unsigned* __restrict__ Wg = (MODE == 1) ? g_w1 : g_w2;

    extern __shared__ unsigned smem_u[];
    unsigned* xs = smem_u;                  // [64][132] tf32
    unsigned* ws = smem_u + 64 * XS_;       // [128][144] tf32
    __shared__ int bkt[64];
    __shared__ float wlf_s[NH_ * L_];

    const int t = threadIdx.x;
    const int lane = t & 31, w = t >> 5;
    const int g4 = lane >> 2, tg = lane & 3;
    const int wm = w >> 2, wn = w & 3;
    const int rbase = wm * 32, cbase = wn * 32;
    const long row0 = (long)blockIdx.x * 64;

    if (MODE == 2) {
        int b = (int)(row0 / N_), n0 = (int)(row0 % N_);
        if (t < NH_ * L_)
            wlf_s[t] = aux0[t] + (float)N_ * aux1[t] + g_wl[b * NH_ * L_ + t];
        __syncthreads();
        const float4* xacc4 = reinterpret_cast<const float4*>(g_xacc);
        const float4* rv4   = reinterpret_cast<const float4*>(g_rv);
        #pragma unroll
        for (int i = 0; i < 8; i++) {
            int idx = t + i * 256;
            int r = idx >> 5, c4 = idx & 31;
            int n = n0 + r;
            int yy = n / HW_, xx = n - yy * HW_;
            const float* wf = wlf_s + (c4 >> 3) * L_;
            float4 y = xacc4[(row0 + r) * 32 + c4];
            #pragma unroll
            for (int l = 0; l < L_; l++) {
                int py = yy + l / 3 - 1, px = xx + l % 3 - 1;
                if (py >= 0 && py < HW_ && px >= 0 && px < HW_) {
                    float4 v = rv4[((long)b * N_ + py * HW_ + px) * 32 + c4];
                    float wl = wf[l];
                    y.x = fmaf(v.x, wl, y.x); y.y = fmaf(v.y, wl, y.y);
                    y.z = fmaf(v.z, wl, y.z); y.w = fmaf(v.w, wl, y.w);
                }
            }
            uint4 u = make_uint4(tf32_of(y.x), tf32_of(y.y), tf32_of(y.z), tf32_of(y.w));
            *reinterpret_cast<uint4*>(xs + r * XS_ + c4 * 4) = u;
        }
    } else {
        const float4* X4 = reinterpret_cast<const float4*>(Xarg + row0 * C_);
        #pragma unroll
        for (int i = 0; i < 8; i++) {
            int idx = t + i * 256;
            int r = idx >> 5, c4 = idx & 31;
            float4 v = X4[idx];
            uint4 u = make_uint4(tf32_of(v.x), tf32_of(v.y), tf32_of(v.z), tf32_of(v.w));
            *reinterpret_cast<uint4*>(xs + r * XS_ + c4 * 4) = u;
        }
    }
    {
        const uint4* W4 = reinterpret_cast<const uint4*>(Wg);
        uint4* ws4 = reinterpret_cast<uint4*>(ws);
        #pragma unroll
        for (int i = 0; i < 18; i++) ws4[t + i * 256] = W4[t + i * 256];
    }
    __syncthreads();

    float acc[2][4][4];
    #pragma unroll
    for (int mt = 0; mt < 2; mt++)
        #pragma unroll
        for (int nt = 0; nt < 4; nt++)
            #pragma unroll
            for (int j = 0; j < 4; j++) acc[mt][nt][j] = 0.f;

    #pragma unroll
    for (int kk = 0; kk < 16; kk++) {
        unsigned a[2][4];
        const unsigned* xa = xs + (rbase + g4) * XS_ + kk * 8 + tg;
        #pragma unroll
        for (int mt = 0; mt < 2; mt++) {
            const unsigned* x2 = xa + mt * 16 * XS_;
            a[mt][0] = x2[0];
            a[mt][1] = x2[8 * XS_];
            a[mt][2] = x2[4];
            a[mt][3] = x2[8 * XS_ + 4];
        }
        const unsigned* wb = ws + (kk * 8 + tg) * WS_ + g4;
        #pragma unroll
        for (int nt = 0; nt < 4; nt++) {
            unsigned b0 = wb[cbase + nt * 8];
            unsigned b1 = wb[4 * WS_ + cbase + nt * 8];
            mma_tf32(acc[0][nt], a[0], b0, b1);
            mma_tf32(acc[1][nt], a[1], b0, b1);
        }
    }

    if (MODE == 1) {
        __syncthreads();
        float* gt = reinterpret_cast<float*>(ws);   // [64][128]
        #pragma unroll
        for (int mt = 0; mt < 2; mt++) {
            #pragma unroll
            for (int nt = 0; nt < 4; nt++) {
                int col = cbase + nt * 8 + 2 * tg;
                float b0 = bias[col], b1 = bias[col + 1];
                #pragma unroll
                for (int half = 0; half < 2; half++) {
                    int r = rbase + mt * 16 + g4 + half * 8;
                    float v0 = gelu_exact(acc[mt][nt][half * 2 + 0] + b0);
                    float v1 = gelu_exact(acc[mt][nt][half * 2 + 1] + b1);
                    *reinterpret_cast<float2*>(gt + r * 128 + col) = make_float2(v0, v1);
                }
            }
        }
        int b = (int)(row0 / N_), n0 = (int)(row0 % N_);
        if (t < 64) {
            int n = n0 + t, y = n / HW_, x = n - y * HW_;
            bkt[t] = (y >> 3) * 7 + (x >> 3);
        }
        __syncthreads();
        int col = t & 127, half = t >> 7;
        int r0 = half * 32;
        float a = 0.f;
        int cur = bkt[r0];
        #pragma unroll 4
        for (int r = r0; r < r0 + 32; r++) {
            int bk = bkt[r];
            if (bk != cur) {
                atomicAdd(&g_xp[((long)b * P_ + cur) * C_ + col], a);
                a = 0.f; cur = bk;
            }
            a += gt[r * 128 + col];
        }
        atomicAdd(&g_xp[((long)b * P_ + cur) * C_ + col], a);
        return;
    }

    #pragma unroll
    for (int mt = 0; mt < 2; mt++) {
        #pragma unroll
        for (int nt = 0; nt < 4; nt++) {
            int col = cbase + nt * 8 + 2 * tg;
            float b0 = bias[col], b1 = bias[col + 1];
            #pragma unroll
            for (int half = 0; half < 2; half++) {
                long rl = row0 + rbase + mt * 16 + g4 + half * 8;
                float v0 = acc[mt][nt][half * 2 + 0] + b0;
                float v1 = acc[mt][nt][half * 2 + 1] + b1;
                *reinterpret_cast<float2*>(Outarg + rl * C_ + col) = make_float2(v0, v1);
            }
        }
    }
}

// ---------------- fused MODE 0 + MODE 3 launch ----------------
// blocks [0,392): rv = relu(x @ vw + vb), extra cols -> q/ksum
// blocks [392,406): pooled kvp, k-split (tile = (bx-392)>>1, ks = (bx-392)&1)
__global__ __launch_bounds__(256) void gemm03_k(const float* __restrict__ X,
                                                const float* __restrict__ vbias,
                                                const float* __restrict__ nw,
                                                const float* __restrict__ nb)
{
    extern __shared__ unsigned smem_u[];
    const int t = threadIdx.x;
    const int lane = t & 31, w = t >> 5;
    const int g4 = lane >> 2, tg = lane & 3;
    const int wm = w >> 2, wn = w & 3;
    const int rbase = wm * 32, cbase = wn * 32;

    float acc[2][4][4];
    #pragma unroll
    for (int mt = 0; mt < 2; mt++)
        #pragma unroll
        for (int nt = 0; nt < 4; nt++)
            #pragma unroll
            for (int j = 0; j < 4; j++) acc[mt][nt][j] = 0.f;
    float accE[2][4];
    #pragma unroll
    for (int mt = 0; mt < 2; mt++)
        #pragma unroll
        for (int j = 0; j < 4; j++) accE[mt][j] = 0.f;

    if (blockIdx.x < 392) {
        // ================= MODE 0 =================
        unsigned* xs = smem_u;                  // [64][132]
        unsigned* ws = smem_u + 64 * XS_;       // [128][144]
        const long row0 = (long)blockIdx.x * 64;

        const float4* X4 = reinterpret_cast<const float4*>(X + row0 * C_);
        #pragma unroll
        for (int i = 0; i < 8; i++) {
            int idx = t + i * 256;
            int r = idx >> 5, c4 = idx & 31;
            float4 v = X4[idx];
            uint4 u = make_uint4(tf32_of(v.x), tf32_of(v.y), tf32_of(v.z), tf32_of(v.w));
            *reinterpret_cast<uint4*>(xs + r * XS_ + c4 * 4) = u;
        }
        {
            const uint4* W4 = reinterpret_cast<const uint4*>(g_w0);
            uint4* ws4 = reinterpret_cast<uint4*>(ws);
            #pragma unroll
            for (int i = 0; i < 18; i++) ws4[t + i * 256] = W4[t + i * 256];
        }
        __syncthreads();

        #pragma unroll
        for (int kk = 0; kk < 16; kk++) {
            unsigned a[2][4];
            const unsigned* xa = xs + (rbase + g4) * XS_ + kk * 8 + tg;
            #pragma unroll
            for (int mt = 0; mt < 2; mt++) {
                const unsigned* x2 = xa + mt * 16 * XS_;
                a[mt][0] = x2[0];
                a[mt][1] = x2[8 * XS_];
                a[mt][2] = x2[4];
                a[mt][3] = x2[8 * XS_ + 4];
            }
            const unsigned* wb = ws + (kk * 8 + tg) * WS_ + g4;
            #pragma unroll
            for (int nt = 0; nt < 4; nt++) {
                unsigned b0 = wb[cbase + nt * 8];
                unsigned b1 = wb[4 * WS_ + cbase + nt * 8];
                mma_tf32(acc[0][nt], a[0], b0, b1);
                mma_tf32(acc[1][nt], a[1], b0, b1);
            }
            if (wn == 0) {
                unsigned b0 = wb[128];
                unsigned b1 = wb[4 * WS_ + 128];
                mma_tf32(accE[0], a[0], b0, b1);
                mma_tf32(accE[1], a[1], b0, b1);
            }
        }

        #pragma unroll
        for (int mt = 0; mt < 2; mt++) {
            #pragma unroll
            for (int nt = 0; nt < 4; nt++) {
                int col = cbase + nt * 8 + 2 * tg;
                float b0 = vbias[col], b1 = vbias[col + 1];
                #pragma unroll
                for (int half = 0; half < 2; half++) {
                    long rl = row0 + rbase + mt * 16 + g4 + half * 8;
                    float v0 = fmaxf(acc[mt][nt][half * 2 + 0] + b0, 0.f);
                    float v1 = fmaxf(acc[mt][nt][half * 2 + 1] + b1, 0.f);
                    *reinterpret_cast<float2*>(g_rv + rl * C_ + col) = make_float2(v0, v1);
                }
            }
        }
        if (wn == 0) {
            #pragma unroll
            for (int mt = 0; mt < 2; mt++) {
                #pragma unroll
                for (int half = 0; half < 2; half++) {
                    long grow = row0 + rbase + mt * 16 + g4 + half * 8;
                    int b = (int)(grow / N_), n = (int)(grow % N_);
                    #pragma unroll
                    for (int j = 0; j < 2; j++) {
                        int col = 128 + 2 * tg + j;
                        float v = accE[mt][half * 2 + j];
                        if (col < 132) {
                            g_q[((long)b * NH_ + (col - 128)) * N_ + n] = v;
                        } else {
                            int h = col - 132;
                            g_ksum[((long)b * NH_ + h) * N_ + n] = v + g_ksb[h];
                        }
                    }
                }
            }
        }
    } else {
        // ================= MODE 3 (k-split) =================
        constexpr int XSM = 68;
        unsigned* xs = smem_u;                  // [64][68]
        unsigned* ws = smem_u + 64 * XSM;       // [64][144]
        int bx = blockIdx.x - 392;
        const int ks = bx & 1;
        const long row0 = (long)(bx >> 1) * 64;

        // inline LN fill: warp w handles rows w + i*8; store only this k-half
        #pragma unroll
        for (int i = 0; i < 8; i++) {
            int r = w + i * 8;
            long grow = row0 + r;
            float4 xn = make_float4(0.f, 0.f, 0.f, 0.f);
            if (grow < BP_) {
                float4 s = reinterpret_cast<const float4*>(g_xp)[grow * 32 + lane];
                s.x *= (1.f/64.f); s.y *= (1.f/64.f); s.z *= (1.f/64.f); s.w *= (1.f/64.f);
                float tot = s.x + s.y + s.z + s.w;
                #pragma unroll
                for (int o = 16; o; o >>= 1) tot += __shfl_xor_sync(~0u, tot, o);
                float mu = tot * (1.f / C_);
                float dx = s.x - mu, dy = s.y - mu, dz = s.z - mu, dw = s.w - mu;
                float sq = dx * dx + dy * dy + dz * dz + dw * dw;
                #pragma unroll
                for (int o = 16; o; o >>= 1) sq += __shfl_xor_sync(~0u, sq, o);
                float inv = rsqrtf(sq * (1.f / C_) + 1e-5f);
                float4 w4 = reinterpret_cast<const float4*>(nw)[lane];
                float4 b4 = reinterpret_cast<const float4*>(nb)[lane];
                xn.x = dx * inv * w4.x + b4.x; xn.y = dy * inv * w4.y + b4.y;
                xn.z = dz * inv * w4.z + b4.z; xn.w = dw * inv * w4.w + b4.w;
            }
            if ((lane >> 4) == ks) {
                int c4h = lane & 15;
                uint4 u = make_uint4(tf32_of(xn.x), tf32_of(xn.y),
                                     tf32_of(xn.z), tf32_of(xn.w));
                *reinterpret_cast<uint4*>(xs + r * XSM + c4h * 4) = u;
            }
        }
        {
            const uint4* W4 = reinterpret_cast<const uint4*>(g_w0) + ks * (64 * WS_ / 4);
            uint4* ws4 = reinterpret_cast<uint4*>(ws);
            #pragma unroll
            for (int i = 0; i < 9; i++) ws4[t + i * 256] = W4[t + i * 256];
        }
        __syncthreads();

        #pragma unroll
        for (int kk = 0; kk < 8; kk++) {
            unsigned a[2][4];
            const unsigned* xa = xs + (rbase + g4) * XSM + kk * 8 + tg;
            #pragma unroll
            for (int mt = 0; mt < 2; mt++) {
                const unsigned* x2 = xa + mt * 16 * XSM;
                a[mt][0] = x2[0];
                a[mt][1] = x2[8 * XSM];
                a[mt][2] = x2[4];
                a[mt][3] = x2[8 * XSM + 4];
            }
            const unsigned* wb = ws + (kk * 8 + tg) * WS_ + g4;
            #pragma unroll
            for (int nt = 0; nt < 4; nt++) {
                unsigned b0 = wb[cbase + nt * 8];
                unsigned b1 = wb[4 * WS_ + cbase + nt * 8];
                mma_tf32(acc[0][nt], a[0], b0, b1);
                mma_tf32(acc[1][nt], a[1], b0, b1);
            }
            if (wn == 0) {
                unsigned b0 = wb[128];
                unsigned b1 = wb[4 * WS_ + 128];
                mma_tf32(accE[0], a[0], b0, b1);
                mma_tf32(accE[1], a[1], b0, b1);
            }
        }

        #pragma unroll
        for (int mt = 0; mt < 2; mt++) {
            #pragma unroll
            for (int nt = 0; nt < 4; nt++) {
                int col = cbase + nt * 8 + 2 * tg;
                float b0 = ks ? 0.f : vbias[col];
                float b1 = ks ? 0.f : vbias[col + 1];
                #pragma unroll
                for (int half = 0; half < 2; half++) {
                    long rl = row0 + rbase + mt * 16 + g4 + half * 8;
                    if (rl < BP_) {
                        int b = (int)(rl / P_), p = (int)(rl % P_);
                        int h = col >> 5, d = col & 31;
                        float* dst = g_vpool + ((b * NH_ + h) * P_ + p) * D_ + d;
                        atomicAdd(dst,     acc[mt][nt][half * 2 + 0] + b0);
                        atomicAdd(dst + 1, acc[mt][nt][half * 2 + 1] + b1);
                    }
                }
            }
        }
        if (wn == 0) {
            #pragma unroll
            for (int mt = 0; mt < 2; mt++) {
                #pragma unroll
                for (int half = 0; half < 2; half++) {
                    long grow = row0 + rbase + mt * 16 + g4 + half * 8;
                    #pragma unroll
                    for (int j = 0; j < 2; j++) {
                        int col = 128 + 2 * tg + j;
                        if (grow < BP_ && col >= 132) {
                            int b = (int)(grow / P_), p = (int)(grow % P_);
                            int h = col - 132;
                            atomicAdd(&g_kpool[(b * NH_ + h) * P_ + p],
                                      accE[mt][half * 2 + j] + (ks ? 0.f : g_ksb[h]));
                        }
                    }
                }
            }
        }
    }
}

// ---------------- K4: denom + per-n 58-way softmax + pool matvec + a_local ----------------
__global__ __launch_bounds__(256) void attn_k(const float* __restrict__ pbp,
                                              const float* __restrict__ pbl)
{
    int bh = blockIdx.y;
    int b  = bh >> 2, h = bh & 3;
    int n0 = blockIdx.x * 64;
    int t = threadIdx.x, lane = t & 31, wid = t >> 5;

    __shared__ float vps[P_ * D_];
    __shared__ float kps[P_];
    __shared__ float asb[8][64];
    __shared__ float wlsh[8][L_];
    __shared__ float sh8[8];

    const float* qp = g_q + (long)bh * N_;
    for (int i = t; i < P_ * D_; i += 256) vps[i] = g_vpool[bh * P_ * D_ + i];
    if (t < P_) kps[t] = g_kpool[bh * P_ + t];

    float s = 0.f;
    for (int n = t; n < N_; n += 256) s += __expf(qp[n]);
    #pragma unroll
    for (int o = 16; o; o >>= 1) s += __shfl_xor_sync(~0u, s, o);
    if (lane == 0) sh8[wid] = s;
    __syncthreads();
    float S = sh8[0];
    #pragma unroll
    for (int ww = 1; ww < 8; ww++) S += sh8[ww];
    float invS = 1.f / S;

    const float NEG = -INFINITY;
    float wlacc = 0.f;
    float pbl_l = (lane < L_) ? pbl[h * L_ + lane] : 0.f;

    for (int i = 0; i < 8; i++) {
        int n = n0 + wid * 8 + i;
        float cs  = __expf(qp[n]) * invS;
        float csS = cs * SCALE_;
        const float* pbpn = pbp + ((long)h * N_ + n) * P_;

        float v0, v1 = NEG;
        if (lane < L_) {
            int y = n / HW_ + lane / 3 - 1, x = n % HW_ + lane % 3 - 1;
            v0 = (y >= 0 && y < HW_ && x >= 0 && x < HW_)
                 ? g_ksum[(long)bh * N_ + y * HW_ + x] * csS + pbl_l : NEG;
        } else {
            int p = lane - L_;
            v0 = csS * kps[p] + pbpn[p];
        }
        if (lane < 26) { int p = lane + 23; v1 = csS * kps[p] + pbpn[p]; }

        float e0 = __expf(v0);
        float e1 = (lane < 26) ? __expf(v1) : 0.f;
        float se = e0 + e1;
        #pragma unroll
        for (int o = 16; o; o >>= 1) se += __shfl_xor_sync(0xffffffffu, se, o);
        float inv = 1.f / se;
        e0 *= inv; e1 *= inv;

        if (lane < L_) wlacc += e0;
        asb[wid][lane] = e0;
        if (lane < 26) asb[wid][lane + 32] = e1;
        __syncwarp();

        float acc = 0.f;
        #pragma unroll
        for (int p = 0; p < P_; p++)
            acc = fmaf(asb[wid][L_ + p], vps[p * D_ + lane], acc);
        g_xacc[((long)b * N_ + n) * C_ + h * D_ + lane] = acc;
        __syncwarp();
    }

    if (lane < L_) wlsh[wid][lane] = wlacc;
    __syncthreads();
    if (t < L_) {
        float sl = 0.f;
        #pragma unroll
        for (int ww = 0; ww < 8; ww++) sl += wlsh[ww][t];
        atomicAdd(&g_wl[bh * L_ + t], sl);
    }
}

// ---------------- launch ----------------
extern "C" void kernel_launch(void* const* d_in, const int* in_sizes, int n_in,
                              void* d_out, int out_size)
{
    const float* x    = (const float*)d_in[0];
    const float* q_w  = (const float*)d_in[1];
    const float* kv_w = (const float*)d_in[4];
    const float* kv_b = (const float*)d_in[5];
    const float* sr_w = (const float*)d_in[6];
    const float* sr_b = (const float*)d_in[7];
    const float* nw   = (const float*)d_in[8];
    const float* nb   = (const float*)d_in[9];
    const float* pbp  = (const float*)d_in[10];
    const float* pbl  = (const float*)d_in[11];
    const float* lt   = (const float*)d_in[12];
    const float* lb   = (const float*)d_in[13];
    const float* pjw  = (const float*)d_in[14];
    const float* pjb  = (const float*)d_in[15];
    float* out = (float*)d_out;

    static bool attr_set = false;
    if (!attr_set) {
        cudaFuncSetAttribute(gemm_k<1>, cudaFuncAttributeMaxDynamicSharedMemorySize, SMEM_GEMM);
        cudaFuncSetAttribute(gemm_k<2>, cudaFuncAttributeMaxDynamicSharedMemorySize, SMEM_GEMM);
        cudaFuncSetAttribute(gemm03_k, cudaFuncAttributeMaxDynamicSharedMemorySize, SMEM_GEMM);
        attr_set = true;
    }

    transpose_k<<<72, 256>>>(kv_w, kv_b, q_w, sr_w, pjw);     // weights + zero accums
    gemm_k<1><<<392, 256, SMEM_GEMM>>>(x, sr_b, nullptr, nullptr, nullptr);  // gelu(sr)+pool
    gemm03_k<<<406, 256, SMEM_GEMM>>>(x, kv_b + C_, nw, nb);  // relu(v)+q+ksum  ∥  LN+kvp
    dim3 g4(49, B_ * NH_);
    attn_k<<<g4, 256>>>(pbp, pbl);                            // denom + softmax + x_pool
    gemm_k<2><<<392, 256, SMEM_GEMM>>>(nullptr, pjb, out, lt, lb);  // wlf+localmix+proj
}

// round 16
// speedup vs baseline: 1.2962x; 1.0370x over previous
#include <cuda_runtime.h>
#include <math.h>

// ---------------- problem constants ----------------
constexpr int B_  = 8;
constexpr int N_  = 3136;   // H*W
constexpr int C_  = 128;
constexpr int NH_ = 4;
constexpr int D_  = 32;     // C/NH
constexpr int L_  = 9;      // WIN*WIN
constexpr int P_  = 49;     // PH*PW
constexpr int HW_ = 56;     // H == W
constexpr int BP_ = B_ * P_;  // 392 pooled rows
constexpr float SCALE_ = 0.08838834764831845f;  // C^-0.5

constexpr int WS_  = 144;   // padded weight column stride (tf32 ext matrices)
constexpr int XS_  = 132;   // padded x-tile row stride
constexpr int SMEM_GEMM = (64 * XS_ + 128 * WS_) * 4;   // 107520 B

// ---------------- device scratch (no allocation allowed) ----------------
__device__ __align__(16) float g_rv   [B_*N_*C_];     // relu(v + bias)
__device__ __align__(16) float g_xacc [B_*N_*C_];     // x_pool per (b,n,c)
__device__ __align__(16) float g_q    [B_*NH_*N_];    // q logits [b][h][n]
__device__ __align__(16) float g_ksum [B_*NH_*N_];    // sum_d k  [b][h][n]
__device__ __align__(16) float g_xp   [BP_*C_];       // pooled sums (pre /64)
__device__ __align__(16) float g_kpool[B_*NH_*P_];
__device__ __align__(16) float g_vpool[B_*NH_*P_*D_];
__device__ float g_wl [B_*NH_*L_];
__device__ float g_ksb[NH_];                          // per-head summed k bias
__device__ __align__(16) unsigned g_w0[C_*WS_];       // tf32 ext: v | qw | ksw | 0
__device__ __align__(16) unsigned g_w1[C_*WS_];       // tf32 ext: sr | 0
__device__ __align__(16) unsigned g_w2[C_*WS_];       // tf32 ext: proj | 0

__device__ __forceinline__ float gelu_exact(float v) {
    return 0.5f * v * (1.0f + erff(v * 0.70710678118654752f));
}
__device__ __forceinline__ unsigned tf32_of(float f) {
    unsigned u; asm("cvt.rna.tf32.f32 %0, %1;" : "=r"(u) : "f"(f)); return u;
}
__device__ __forceinline__ void mma_tf32(float* c, const unsigned* a,
                                         unsigned b0, unsigned b1) {
    asm volatile("mma.sync.aligned.m16n8k8.row.col.f32.tf32.tf32.f32 "
        "{%0,%1,%2,%3}, {%4,%5,%6,%7}, {%8,%9}, {%0,%1,%2,%3};"
        : "+f"(c[0]), "+f"(c[1]), "+f"(c[2]), "+f"(c[3])
        : "r"(a[0]), "r"(a[1]), "r"(a[2]), "r"(a[3]), "r"(b0), "r"(b1));
}

// ---------------- K0: weight prep + zero accumulators ----------------
__global__ void transpose_k(const float* __restrict__ kvw,
                            const float* __restrict__ kvb,
                            const float* __restrict__ qw,
                            const float* __restrict__ srw,
                            const float* __restrict__ pjw)
{
    int i = blockIdx.x * 256 + threadIdx.x;      // 72 blocks cover 128*144
    for (int j = i; j < BP_ * C_; j += 72 * 256) g_xp[j] = 0.f;
    for (int j = i; j < B_ * NH_ * P_ * D_; j += 72 * 256) g_vpool[j] = 0.f;
    if (i < B_ * NH_ * P_) g_kpool[i] = 0.f;
    if (i < B_ * NH_ * L_) g_wl[i] = 0.f;
    if (i >= C_ * WS_) return;
    int k = i / WS_, c = i % WS_;
    float v0 = 0.f, v1 = 0.f, v2 = 0.f;
    if (c < 128) {
        v0 = kvw[(128 + c) * 128 + k];           // v rows of kv_w
        v1 = srw[c * 128 + k];
        v2 = pjw[c * 128 + k];
    } else if (c < 132) {
        v0 = qw[(c - 128) * 128 + k];
    } else if (c < 136) {
        float s = 0.f;
        #pragma unroll
        for (int j = 0; j < D_; j++) s += kvw[((c - 132) * D_ + j) * 128 + k];
        v0 = s;
    }
    g_w0[i] = tf32_of(v0);
    g_w1[i] = tf32_of(v1);
    g_w2[i] = tf32_of(v2);
    if (i < NH_) {
        float s = 0.f;
        #pragma unroll
        for (int j = 0; j < D_; j++) s += kvb[i * D_ + j];
        g_ksb[i] = s;
    }
}

// ---------------- tf32 mma GEMM (modes 1 & 2) ----------------
// MODE 1: gelu(x @ srw + b) -> pooled sums into g_xp (atomicAdd)
// MODE 2: out = (xacc + localmix) @ proj + b; aux0/1 = lt/lb (wlf inline)
template<int MODE>
__global__ __launch_bounds__(256) void gemm_k(const float* __restrict__ Xarg,
                                              const float* __restrict__ bias,
                                              float* __restrict__ Outarg,
                                              const float* __restrict__ aux0,
                                              const float* __restrict__ aux1)
{
    const unsigned* __restrict__ Wg = (MODE == 1) ? g_w1 : g_w2;

    extern __shared__ unsigned smem_u[];
    unsigned* xs = smem_u;                  // [64][132] tf32
    unsigned* ws = smem_u + 64 * XS_;       // [128][144] tf32
    __shared__ int bkt[64];
    __shared__ float wlf_s[NH_ * L_];

    const int t = threadIdx.x;
    const int lane = t & 31, w = t >> 5;
    const int g4 = lane >> 2, tg = lane & 3;
    const int wm = w >> 2, wn = w & 3;
    const int rbase = wm * 32, cbase = wn * 32;
    const long row0 = (long)blockIdx.x * 64;

    if (MODE == 2) {
        int b = (int)(row0 / N_), n0 = (int)(row0 % N_);
        if (t < NH_ * L_)
            wlf_s[t] = aux0[t] + (float)N_ * aux1[t] + g_wl[b * NH_ * L_ + t];
        __syncthreads();
        const float4* xacc4 = reinterpret_cast<const float4*>(g_xacc);
        const float4* rv4   = reinterpret_cast<const float4*>(g_rv);
        #pragma unroll
        for (int i = 0; i < 8; i++) {
            int idx = t + i * 256;
            int r = idx >> 5, c4 = idx & 31;
            int n = n0 + r;
            int yy = n / HW_, xx = n - yy * HW_;
            const float* wf = wlf_s + (c4 >> 3) * L_;
            float4 y = xacc4[(row0 + r) * 32 + c4];
            #pragma unroll
            for (int l = 0; l < L_; l++) {
                int py = yy + l / 3 - 1, px = xx + l % 3 - 1;
                if (py >= 0 && py < HW_ && px >= 0 && px < HW_) {
                    float4 v = rv4[((long)b * N_ + py * HW_ + px) * 32 + c4];
                    float wl = wf[l];
                    y.x = fmaf(v.x, wl, y.x); y.y = fmaf(v.y, wl, y.y);
                    y.z = fmaf(v.z, wl, y.z); y.w = fmaf(v.w, wl, y.w);
                }
            }
            uint4 u = make_uint4(tf32_of(y.x), tf32_of(y.y), tf32_of(y.z), tf32_of(y.w));
            *reinterpret_cast<uint4*>(xs + r * XS_ + c4 * 4) = u;
        }
    } else {
        const float4* X4 = reinterpret_cast<const float4*>(Xarg + row0 * C_);
        #pragma unroll
        for (int i = 0; i < 8; i++) {
            int idx = t + i * 256;
            int r = idx >> 5, c4 = idx & 31;
            float4 v = X4[idx];
            uint4 u = make_uint4(tf32_of(v.x), tf32_of(v.y), tf32_of(v.z), tf32_of(v.w));
            *reinterpret_cast<uint4*>(xs + r * XS_ + c4 * 4) = u;
        }
    }
    {
        const uint4* W4 = reinterpret_cast<const uint4*>(Wg);
        uint4* ws4 = reinterpret_cast<uint4*>(ws);
        #pragma unroll
        for (int i = 0; i < 18; i++) ws4[t + i * 256] = W4[t + i * 256];
    }
    __syncthreads();

    float acc[2][4][4];
    #pragma unroll
    for (int mt = 0; mt < 2; mt++)
        #pragma unroll
        for (int nt = 0; nt < 4; nt++)
            #pragma unroll
            for (int j = 0; j < 4; j++) acc[mt][nt][j] = 0.f;

    #pragma unroll
    for (int kk = 0; kk < 16; kk++) {
        unsigned a[2][4];
        const unsigned* xa = xs + (rbase + g4) * XS_ + kk * 8 + tg;
        #pragma unroll
        for (int mt = 0; mt < 2; mt++) {
            const unsigned* x2 = xa + mt * 16 * XS_;
            a[mt][0] = x2[0];
            a[mt][1] = x2[8 * XS_];
            a[mt][2] = x2[4];
            a[mt][3] = x2[8 * XS_ + 4];
        }
        const unsigned* wb = ws + (kk * 8 + tg) * WS_ + g4;
        #pragma unroll
        for (int nt = 0; nt < 4; nt++) {
            unsigned b0 = wb[cbase + nt * 8];
            unsigned b1 = wb[4 * WS_ + cbase + nt * 8];
            mma_tf32(acc[0][nt], a[0], b0, b1);
            mma_tf32(acc[1][nt], a[1], b0, b1);
        }
    }

    if (MODE == 1) {
        __syncthreads();
        float* gt = reinterpret_cast<float*>(ws);   // [64][128]
        #pragma unroll
        for (int mt = 0; mt < 2; mt++) {
            #pragma unroll
            for (int nt = 0; nt < 4; nt++) {
                int col = cbase + nt * 8 + 2 * tg;
                float b0 = bias[col], b1 = bias[col + 1];
                #pragma unroll
                for (int half = 0; half < 2; half++) {
                    int r = rbase + mt * 16 + g4 + half * 8;
                    float v0 = gelu_exact(acc[mt][nt][half * 2 + 0] + b0);
                    float v1 = gelu_exact(acc[mt][nt][half * 2 + 1] + b1);
                    *reinterpret_cast<float2*>(gt + r * 128 + col) = make_float2(v0, v1);
                }
            }
        }
        int b = (int)(row0 / N_), n0 = (int)(row0 % N_);
        if (t < 64) {
            int n = n0 + t, y = n / HW_, x = n - y * HW_;
            bkt[t] = (y >> 3) * 7 + (x >> 3);
        }
        __syncthreads();
        int col = t & 127, half = t >> 7;
        int r0 = half * 32;
        float a = 0.f;
        int cur = bkt[r0];
        #pragma unroll 4
        for (int r = r0; r < r0 + 32; r++) {
            int bk = bkt[r];
            if (bk != cur) {
                atomicAdd(&g_xp[((long)b * P_ + cur) * C_ + col], a);
                a = 0.f; cur = bk;
            }
            a += gt[r * 128 + col];
        }
        atomicAdd(&g_xp[((long)b * P_ + cur) * C_ + col], a);
        return;
    }

    #pragma unroll
    for (int mt = 0; mt < 2; mt++) {
        #pragma unroll
        for (int nt = 0; nt < 4; nt++) {
            int col = cbase + nt * 8 + 2 * tg;
            float b0 = bias[col], b1 = bias[col + 1];
            #pragma unroll
            for (int half = 0; half < 2; half++) {
                long rl = row0 + rbase + mt * 16 + g4 + half * 8;
                float v0 = acc[mt][nt][half * 2 + 0] + b0;
                float v1 = acc[mt][nt][half * 2 + 1] + b1;
                *reinterpret_cast<float2*>(Outarg + rl * C_ + col) = make_float2(v0, v1);
            }
        }
    }
}

// ---------------- fused MODE 0 + MODE 3 launch ----------------
__global__ __launch_bounds__(256) void gemm03_k(const float* __restrict__ X,
                                                const float* __restrict__ vbias,
                                                const float* __restrict__ nw,
                                                const float* __restrict__ nb)
{
    extern __shared__ unsigned smem_u[];
    const int t = threadIdx.x;
    const int lane = t & 31, w = t >> 5;
    const int g4 = lane >> 2, tg = lane & 3;
    const int wm = w >> 2, wn = w & 3;
    const int rbase = wm * 32, cbase = wn * 32;

    float acc[2][4][4];
    #pragma unroll
    for (int mt = 0; mt < 2; mt++)
        #pragma unroll
        for (int nt = 0; nt < 4; nt++)
            #pragma unroll
            for (int j = 0; j < 4; j++) acc[mt][nt][j] = 0.f;
    float accE[2][4];
    #pragma unroll
    for (int mt = 0; mt < 2; mt++)
        #pragma unroll
        for (int j = 0; j < 4; j++) accE[mt][j] = 0.f;

    if (blockIdx.x < 392) {
        // ================= MODE 0 =================
        unsigned* xs = smem_u;                  // [64][132]
        unsigned* ws = smem_u + 64 * XS_;       // [128][144]
        const long row0 = (long)blockIdx.x * 64;

        const float4* X4 = reinterpret_cast<const float4*>(X + row0 * C_);
        #pragma unroll
        for (int i = 0; i < 8; i++) {
            int idx = t + i * 256;
            int r = idx >> 5, c4 = idx & 31;
            float4 v = X4[idx];
            uint4 u = make_uint4(tf32_of(v.x), tf32_of(v.y), tf32_of(v.z), tf32_of(v.w));
            *reinterpret_cast<uint4*>(xs + r * XS_ + c4 * 4) = u;
        }
        {
            const uint4* W4 = reinterpret_cast<const uint4*>(g_w0);
            uint4* ws4 = reinterpret_cast<uint4*>(ws);
            #pragma unroll
            for (int i = 0; i < 18; i++) ws4[t + i * 256] = W4[t + i * 256];
        }
        __syncthreads();

        #pragma unroll
        for (int kk = 0; kk < 16; kk++) {
            unsigned a[2][4];
            const unsigned* xa = xs + (rbase + g4) * XS_ + kk * 8 + tg;
            #pragma unroll
            for (int mt = 0; mt < 2; mt++) {
                const unsigned* x2 = xa + mt * 16 * XS_;
                a[mt][0] = x2[0];
                a[mt][1] = x2[8 * XS_];
                a[mt][2] = x2[4];
                a[mt][3] = x2[8 * XS_ + 4];
            }
            const unsigned* wb = ws + (kk * 8 + tg) * WS_ + g4;
            #pragma unroll
            for (int nt = 0; nt < 4; nt++) {
                unsigned b0 = wb[cbase + nt * 8];
                unsigned b1 = wb[4 * WS_ + cbase + nt * 8];
                mma_tf32(acc[0][nt], a[0], b0, b1);
                mma_tf32(acc[1][nt], a[1], b0, b1);
            }
            if (wn == 0) {
                unsigned b0 = wb[128];
                unsigned b1 = wb[4 * WS_ + 128];
                mma_tf32(accE[0], a[0], b0, b1);
                mma_tf32(accE[1], a[1], b0, b1);
            }
        }

        #pragma unroll
        for (int mt = 0; mt < 2; mt++) {
            #pragma unroll
            for (int nt = 0; nt < 4; nt++) {
                int col = cbase + nt * 8 + 2 * tg;
                float b0 = vbias[col], b1 = vbias[col + 1];
                #pragma unroll
                for (int half = 0; half < 2; half++) {
                    long rl = row0 + rbase + mt * 16 + g4 + half * 8;
                    float v0 = fmaxf(acc[mt][nt][half * 2 + 0] + b0, 0.f);
                    float v1 = fmaxf(acc[mt][nt][half * 2 + 1] + b1, 0.f);
                    *reinterpret_cast<float2*>(g_rv + rl * C_ + col) = make_float2(v0, v1);
                }
            }
        }
        if (wn == 0) {
            #pragma unroll
            for (int mt = 0; mt < 2; mt++) {
                #pragma unroll
                for (int half = 0; half < 2; half++) {
                    long grow = row0 + rbase + mt * 16 + g4 + half * 8;
                    int b = (int)(grow / N_), n = (int)(grow % N_);
                    #pragma unroll
                    for (int j = 0; j < 2; j++) {
                        int col = 128 + 2 * tg + j;
                        float v = accE[mt][half * 2 + j];
                        if (col < 132) {
                            g_q[((long)b * NH_ + (col - 128)) * N_ + n] = v;
                        } else {
                            int h = col - 132;
                            g_ksum[((long)b * NH_ + h) * N_ + n] = v + g_ksb[h];
                        }
                    }
                }
            }
        }
    } else {
        // ================= MODE 3 (k-split) =================
        constexpr int XSM = 68;
        unsigned* xs = smem_u;                  // [64][68]
        unsigned* ws = smem_u + 64 * XSM;       // [64][144]
        int bx = blockIdx.x - 392;
        const int ks = bx & 1;
        const long row0 = (long)(bx >> 1) * 64;

        #pragma unroll
        for (int i = 0; i < 8; i++) {
            int r = w + i * 8;
            long grow = row0 + r;
            float4 xn = make_float4(0.f, 0.f, 0.f, 0.f);
            if (grow < BP_) {
                float4 s = reinterpret_cast<const float4*>(g_xp)[grow * 32 + lane];
                s.x *= (1.f/64.f); s.y *= (1.f/64.f); s.z *= (1.f/64.f); s.w *= (1.f/64.f);
                float tot = s.x + s.y + s.z + s.w;
                #pragma unroll
                for (int o = 16; o; o >>= 1) tot += __shfl_xor_sync(~0u, tot, o);
                float mu = tot * (1.f / C_);
                float dx = s.x - mu, dy = s.y - mu, dz = s.z - mu, dw = s.w - mu;
                float sq = dx * dx + dy * dy + dz * dz + dw * dw;
                #pragma unroll
                for (int o = 16; o; o >>= 1) sq += __shfl_xor_sync(~0u, sq, o);
                float inv = rsqrtf(sq * (1.f / C_) + 1e-5f);
                float4 w4 = reinterpret_cast<const float4*>(nw)[lane];
                float4 b4 = reinterpret_cast<const float4*>(nb)[lane];
                xn.x = dx * inv * w4.x + b4.x; xn.y = dy * inv * w4.y + b4.y;
                xn.z = dz * inv * w4.z + b4.z; xn.w = dw * inv * w4.w + b4.w;
            }
            if ((lane >> 4) == ks) {
                int c4h = lane & 15;
                uint4 u = make_uint4(tf32_of(xn.x), tf32_of(xn.y),
                                     tf32_of(xn.z), tf32_of(xn.w));
                *reinterpret_cast<uint4*>(xs + r * XSM + c4h * 4) = u;
            }
        }
        {
            const uint4* W4 = reinterpret_cast<const uint4*>(g_w0) + ks * (64 * WS_ / 4);
            uint4* ws4 = reinterpret_cast<uint4*>(ws);
            #pragma unroll
            for (int i = 0; i < 9; i++) ws4[t + i * 256] = W4[t + i * 256];
        }
        __syncthreads();

        #pragma unroll
        for (int kk = 0; kk < 8; kk++) {
            unsigned a[2][4];
            const unsigned* xa = xs + (rbase + g4) * XSM + kk * 8 + tg;
            #pragma unroll
            for (int mt = 0; mt < 2; mt++) {
                const unsigned* x2 = xa + mt * 16 * XSM;
                a[mt][0] = x2[0];
                a[mt][1] = x2[8 * XSM];
                a[mt][2] = x2[4];
                a[mt][3] = x2[8 * XSM + 4];
            }
            const unsigned* wb = ws + (kk * 8 + tg) * WS_ + g4;
            #pragma unroll
            for (int nt = 0; nt < 4; nt++) {
                unsigned b0 = wb[cbase + nt * 8];
                unsigned b1 = wb[4 * WS_ + cbase + nt * 8];
                mma_tf32(acc[0][nt], a[0], b0, b1);
                mma_tf32(acc[1][nt], a[1], b0, b1);
            }
            if (wn == 0) {
                unsigned b0 = wb[128];
                unsigned b1 = wb[4 * WS_ + 128];
                mma_tf32(accE[0], a[0], b0, b1);
                mma_tf32(accE[1], a[1], b0, b1);
            }
        }

        #pragma unroll
        for (int mt = 0; mt < 2; mt++) {
            #pragma unroll
            for (int nt = 0; nt < 4; nt++) {
                int col = cbase + nt * 8 + 2 * tg;
                float b0 = ks ? 0.f : vbias[col];
                float b1 = ks ? 0.f : vbias[col + 1];
                #pragma unroll
                for (int half = 0; half < 2; half++) {
                    long rl = row0 + rbase + mt * 16 + g4 + half * 8;
                    if (rl < BP_) {
                        int b = (int)(rl / P_), p = (int)(rl % P_);
                        int h = col >> 5, d = col & 31;
                        float* dst = g_vpool + ((b * NH_ + h) * P_ + p) * D_ + d;
                        atomicAdd(dst,     acc[mt][nt][half * 2 + 0] + b0);
                        atomicAdd(dst + 1, acc[mt][nt][half * 2 + 1] + b1);
                    }
                }
            }
        }
        if (wn == 0) {
            #pragma unroll
            for (int mt = 0; mt < 2; mt++) {
                #pragma unroll
                for (int half = 0; half < 2; half++) {
                    long grow = row0 + rbase + mt * 16 + g4 + half * 8;
                    #pragma unroll
                    for (int j = 0; j < 2; j++) {
                        int col = 128 + 2 * tg + j;
                        if (grow < BP_ && col >= 132) {
                            int b = (int)(grow / P_), p = (int)(grow % P_);
                            int h = col - 132;
                            atomicAdd(&g_kpool[(b * NH_ + h) * P_ + p],
                                      accE[mt][half * 2 + j] + (ks ? 0.f : g_ksb[h]));
                        }
                    }
                }
            }
        }
    }
}

// ---------------- K4: denom + 58-way softmax + reg-cached pool matvec ----------------
__global__ __launch_bounds__(256) void attn_k(const float* __restrict__ pbp,
                                              const float* __restrict__ pbl)
{
    int bh = blockIdx.y;
    int b  = bh >> 2, h = bh & 3;
    int n0 = blockIdx.x * 64;
    int t = threadIdx.x, lane = t & 31, wid = t >> 5;

    __shared__ float kps[P_ + 1];
    __shared__ __align__(16) float apool[8][52];   // pool probs, p-indexed (8B aligned)
    __shared__ float wlsh[8][L_];
    __shared__ float sh8[8];

    // register-cached v_pool column: vreg[p] = vpool[p][lane], loop-invariant
    float vreg[P_];
    {
        const float* vp = g_vpool + (long)bh * P_ * D_ + lane;
        #pragma unroll
        for (int p = 0; p < P_; p++) vreg[p] = vp[p * D_];
    }
    if (t < P_) kps[t] = g_kpool[bh * P_ + t];

    // context-softmax denominator (per-block recompute, no max shift)
    const float* qp = g_q + (long)bh * N_;
    float s = 0.f;
    for (int n = t; n < N_; n += 256) s += __expf(qp[n]);
    #pragma unroll
    for (int o = 16; o; o >>= 1) s += __shfl_xor_sync(~0u, s, o);
    if (lane == 0) sh8[wid] = s;
    __syncthreads();
    float S = sh8[0];
    #pragma unroll
    for (int ww = 1; ww < 8; ww++) S += sh8[ww];
    float invS = 1.f / S;

    const float NEG = -INFINITY;
    float wlacc = 0.f;
    float pbl_l = (lane < L_) ? pbl[h * L_ + lane] : 0.f;

    for (int i = 0; i < 8; i++) {
        int n = n0 + wid * 8 + i;
        float cs  = __expf(qp[n]) * invS;
        float csS = cs * SCALE_;
        const float* pbpn = pbp + ((long)h * N_ + n) * P_;

        float v0, v1 = NEG;
        if (lane < L_) {
            int y = n / HW_ + lane / 3 - 1, x = n % HW_ + lane % 3 - 1;
            v0 = (y >= 0 && y < HW_ && x >= 0 && x < HW_)
                 ? g_ksum[(long)bh * N_ + y * HW_ + x] * csS + pbl_l : NEG;
        } else {
            int p = lane - L_;
            v0 = csS * kps[p] + pbpn[p];
        }
        if (lane < 26) { int p = lane + 23; v1 = csS * kps[p] + pbpn[p]; }

        float e0 = __expf(v0);
        float e1 = (lane < 26) ? __expf(v1) : 0.f;
        float se = e0 + e1;
        #pragma unroll
        for (int o = 16; o; o >>= 1) se += __shfl_xor_sync(0xffffffffu, se, o);
        float inv = 1.f / se;
        e0 *= inv; e1 *= inv;

        if (lane < L_) wlacc += e0;                 // local probs tally (registers)
        else           apool[wid][lane - L_] = e0;  // pool probs, p-indexed
        if (lane < 26) apool[wid][lane + 23] = e1;
        __syncwarp();

        // x_pool[d=lane] = sum_p apool[p] * vreg[p]  (float2 broadcasts, 4 accums)
        const float2* ap = reinterpret_cast<const float2*>(apool[wid]);
        float a0 = 0.f, a1 = 0.f, a2 = 0.f, a3 = 0.f;
        #pragma unroll
        for (int p2 = 0; p2 < 24; p2 += 2) {
            float2 x0 = ap[p2], x1 = ap[p2 + 1];
            a0 = fmaf(x0.x, vreg[2 * p2 + 0], a0);
            a1 = fmaf(x0.y, vreg[2 * p2 + 1], a1);
            a2 = fmaf(x1.x, vreg[2 * p2 + 2], a2);
            a3 = fmaf(x1.y, vreg[2 * p2 + 3], a3);
        }
        float acc = (a0 + a1) + (a2 + a3) + apool[wid][48] * vreg[48];
        g_xacc[((long)b * N_ + n) * C_ + h * D_ + lane] = acc;
        __syncwarp();
    }

    if (lane < L_) wlsh[wid][lane] = wlacc;
    __syncthreads();
    if (t < L_) {
        float sl = 0.f;
        #pragma unroll
        for (int ww = 0; ww < 8; ww++) sl += wlsh[ww][t];
        atomicAdd(&g_wl[bh * L_ + t], sl);
    }
}

// ---------------- launch ----------------
extern "C" void kernel_launch(void* const* d_in, const int* in_sizes, int n_in,
                              void* d_out, int out_size)
{
    const float* x    = (const float*)d_in[0];
    const float* q_w  = (const float*)d_in[1];
    const float* kv_w = (const float*)d_in[4];
    const float* kv_b = (const float*)d_in[5];
    const float* sr_w = (const float*)d_in[6];
    const float* sr_b = (const float*)d_in[7];
    const float* nw   = (const float*)d_in[8];
    const float* nb   = (const float*)d_in[9];
    const float* pbp  = (const float*)d_in[10];
    const float* pbl  = (const float*)d_in[11];
    const float* lt   = (const float*)d_in[12];
    const float* lb   = (const float*)d_in[13];
    const float* pjw  = (const float*)d_in[14];
    const float* pjb  = (const float*)d_in[15];
    float* out = (float*)d_out;

    static bool attr_set = false;
    if (!attr_set) {
        cudaFuncSetAttribute(gemm_k<1>, cudaFuncAttributeMaxDynamicSharedMemorySize, SMEM_GEMM);
        cudaFuncSetAttribute(gemm_k<2>, cudaFuncAttributeMaxDynamicSharedMemorySize, SMEM_GEMM);
        cudaFuncSetAttribute(gemm03_k, cudaFuncAttributeMaxDynamicSharedMemorySize, SMEM_GEMM);
        attr_set = true;
    }

    transpose_k<<<72, 256>>>(kv_w, kv_b, q_w, sr_w, pjw);     // weights + zero accums
    gemm_k<1><<<392, 256, SMEM_GEMM>>>(x, sr_b, nullptr, nullptr, nullptr);  // gelu(sr)+pool
    gemm03_k<<<406, 256, SMEM_GEMM>>>(x, kv_b + C_, nw, nb);  // relu(v)+q+ksum ∥ LN+kvp
    dim3 g4(49, B_ * NH_);
    attn_k<<<g4, 256>>>(pbp, pbl);                            // denom + softmax + x_pool
    gemm_k<2><<<392, 256, SMEM_GEMM>>>(nullptr, pjb, out, lt, lb);  // wlf+localmix+proj
}